// round 1
// baseline (speedup 1.0000x reference)
#include <cuda_runtime.h>
#include <math.h>

#define NN 100000
#define EE 1600000
#define NW (NN*32)

// ---------------- device scratch (static, no allocation) ----------------
__device__ __align__(16) float g_feats[11][NW];   // h after init + each layer
__device__ __align__(16) float g_preA[NW];        // pre-BN buffer A (msg pre)
__device__ __align__(16) float g_preB[NW];        // pre-BN buffer B (update pre)
__device__ __align__(16) float g_agg[NW];         // edge-aggregated messages
__device__ float g_stats[22][64];                 // [slot][0:32]=sum, [32:64]=sumsq
__device__ __align__(16) float g_scale[22][32];   // fused BN scale  = gamma*istd
__device__ __align__(16) float g_shift[22][32];   // fused BN shift  = beta - mean*scale
__device__ __align__(16) float g_h256[NN*256];
__device__ __align__(16) float g_h128[NN*128];
__device__ __align__(16) float g_h64[NN*64];
__device__ __align__(16) float g_h32[NW];

__device__ __forceinline__ float lrelu(float x){ return x > 0.f ? x : 0.01f*x; }

// ---------------- zero kernels ----------------
__global__ void k_zero_stats(){
  int i = blockIdx.x*blockDim.x + threadIdx.x;
  if (i < 22*64) ((float*)g_stats)[i] = 0.f;
}
__global__ void k_zero_agg(){
  float4* p = (float4*)g_agg;
  const int n4 = NW/4;
  int stride = gridDim.x*blockDim.x;
  for (int i = blockIdx.x*blockDim.x + threadIdx.x; i < n4; i += stride)
    p[i] = make_float4(0.f,0.f,0.f,0.f);
}

// ---------------- per-block column-stat commit ----------------
// thread layout requirement: lane (tid&31) == column
__device__ __forceinline__ void stats_commit(float s, float sq, int slot){
  __shared__ float red[2][8][32];
  int c = threadIdx.x & 31, w = threadIdx.x >> 5;
  red[0][w][c] = s; red[1][w][c] = sq;
  __syncthreads();
  if (w == 0){
    float a = 0.f, b = 0.f;
#pragma unroll
    for (int j = 0; j < 8; j++){ a += red[0][j][c]; b += red[1][j][c]; }
    atomicAdd(&g_stats[slot][c],    a);
    atomicAdd(&g_stats[slot][32+c], b);
  }
}

// ---------------- init layer 0: pre = x * Wi0 + bi0, stats slot 0 ----------------
__global__ void k_init0(const float* __restrict__ x, const float* __restrict__ W0,
                        const float* __restrict__ b0){
  int c = threadIdx.x & 31;
  float wc = W0[c], bc = b0[c];
  float s = 0.f, sq = 0.f;
  int stride = gridDim.x*blockDim.x;
  for (int idx = blockIdx.x*blockDim.x + threadIdx.x; idx < NW; idx += stride){
    float v = fmaf(x[idx >> 5], wc, bc);
    g_preA[idx] = v; s += v; sq += v*v;
  }
  stats_commit(s, sq, 0);
}

// ---------------- finalize BN stats into fused scale/shift ----------------
__global__ void k_finalize(int slot, const float* __restrict__ g,
                           const float* __restrict__ be){
  int c = threadIdx.x;
  float m = g_stats[slot][c] * (1.f/NN);
  float v = g_stats[slot][32+c] * (1.f/NN) - m*m;
  float istd = rsqrtf(v + 1e-5f);
  float sc = g[c]*istd;
  g_scale[slot][c] = sc;
  g_shift[slot][c] = fmaf(-m, sc, be[c]);
}

// ---------------- small GEMM: out[N,32] = act(in)[N,K] @ W[K,32] + b, with stats ----
// K=32: in = feats[fidx] (already activated)  |  PRE: in = bnlrelu(g_preA, preslot)
// K=64: in = concat(feats[fidx], g_agg)
template<int K, bool PRE>
__global__ void __launch_bounds__(256) k_gemm(int fidx, const float* __restrict__ Wg,
        const float* __restrict__ bias, int outsel, int preslot, int outslot)
{
  __shared__ float in_sh[32][K+4];   // stride K+4 == 4 (mod 32): LDS.128 conflict-free
  __shared__ float wT[32][K+4];
  const float* in1 = PRE ? g_preA : g_feats[fidx];
  float* out = outsel ? g_preB : g_preA;
  int tid = threadIdx.x, c = tid & 31, w = tid >> 5;
  int row0 = blockIdx.x * 32;                 // NN % 32 == 0
  for (int i = tid; i < K*32; i += 256){      // wT[c][k] = W[k][c]
    int k = i >> 5, cc = i & 31;
    wT[cc][k] = Wg[i];
  }
  for (int i = tid; i < 1024; i += 256){
    int r = i >> 5, k = i & 31;
    float v = in1[(row0 + r)*32 + k];
    if (PRE) v = lrelu(fmaf(v, g_scale[preslot][k], g_shift[preslot][k]));
    in_sh[r][k] = v;
  }
  if (K == 64){
    for (int i = tid; i < 1024; i += 256){
      int r = i >> 5, k = i & 31;
      in_sh[r][32 + k] = g_agg[(row0 + r)*32 + k];
    }
  }
  __syncthreads();
  int r0 = w * 4;
  float b = bias[c];
  float a0 = b, a1 = b, a2 = b, a3 = b;
#pragma unroll
  for (int k = 0; k < K; k += 4){
    float4 wv = *(const float4*)&wT[c][k];
    float4 x0 = *(const float4*)&in_sh[r0  ][k];
    float4 x1 = *(const float4*)&in_sh[r0+1][k];
    float4 x2 = *(const float4*)&in_sh[r0+2][k];
    float4 x3 = *(const float4*)&in_sh[r0+3][k];
    a0 += x0.x*wv.x + x0.y*wv.y + x0.z*wv.z + x0.w*wv.w;
    a1 += x1.x*wv.x + x1.y*wv.y + x1.z*wv.z + x1.w*wv.w;
    a2 += x2.x*wv.x + x2.y*wv.y + x2.z*wv.z + x2.w*wv.w;
    a3 += x3.x*wv.x + x3.y*wv.y + x3.z*wv.z + x3.w*wv.w;
  }
  out[(row0+r0  )*32+c] = a0;
  out[(row0+r0+1)*32+c] = a1;
  out[(row0+r0+2)*32+c] = a2;
  out[(row0+r0+3)*32+c] = a3;
  float s  = a0+a1+a2+a3;
  float sq = a0*a0+a1*a1+a2*a2+a3*a3;
  stats_commit(s, sq, outslot);
}

// ---------------- apply BN+lrelu (+residual) to g_preB -> feats[oidx] ----------------
__global__ void k_actstore(int slot, int ridx, int oidx){
  int c = threadIdx.x & 31;
  float sc = g_scale[slot][c], sh = g_shift[slot][c];
  const float* resid = (ridx >= 0) ? g_feats[ridx] : (const float*)0;
  float* dstp = g_feats[oidx];
  int stride = gridDim.x*blockDim.x;
  for (int i = blockIdx.x*blockDim.x + threadIdx.x; i < NW; i += stride){
    float v = lrelu(fmaf(g_preB[i], sc, sh));
    if (ridx >= 0) v += resid[i];
    dstp[i] = v;
  }
}

// ---------------- edge kernel: agg[dst] += lrelu(bn(pre[src])) ----------------
// 8 threads per edge, one float4 each, vector RED
__global__ void k_edge(int slot, const int* __restrict__ src, const int* __restrict__ dst){
  int i = blockIdx.x*blockDim.x + threadIdx.x;
  if (i >= EE*8) return;
  int e = i >> 3, q = i & 7;
  int s = __ldg(&src[e]);
  int d = __ldg(&dst[e]);
  float4 v  = ((const float4*)g_preA)[s*8 + q];
  float4 sc = ((const float4*)g_scale[slot])[q];
  float4 sh = ((const float4*)g_shift[slot])[q];
  float m0 = lrelu(fmaf(v.x, sc.x, sh.x));
  float m1 = lrelu(fmaf(v.y, sc.y, sh.y));
  float m2 = lrelu(fmaf(v.z, sc.z, sh.z));
  float m3 = lrelu(fmaf(v.w, sc.w, sh.w));
  float* p = g_agg + (size_t)d*32 + q*4;
  asm volatile("red.global.add.v4.f32 [%0], {%1,%2,%3,%4};"
               :: "l"(p), "f"(m0), "f"(m1), "f"(m2), "f"(m3) : "memory");
}

// ---------------- final MLP tiled GEMM (no BN): out = lrelu(in @ W + b) -------------
template<int L> struct MC;
template<> struct MC<0>{ static constexpr int K=32,  C=256, KC=32;  };
template<> struct MC<1>{ static constexpr int K=256, C=128, KC=64;  };
template<> struct MC<2>{ static constexpr int K=128, C=64,  KC=128; };
template<> struct MC<3>{ static constexpr int K=64,  C=32,  KC=64;  };

template<int L>
__global__ void __launch_bounds__(256) k_mlp(const float* __restrict__ Wg,
                                             const float* __restrict__ bias)
{
  constexpr int K = MC<L>::K, C = MC<L>::C, KC = MC<L>::KC;
  constexpr int PR = 32;           // rows per thread
  constexpr int RSUB = 256/C;      // row groups per block
  constexpr int RT = PR*RSUB;      // rows per block tile
  const float* in = (L==0)? g_feats[10] : (L==1)? g_h256 : (L==2)? g_h128 : g_h64;
  float* out      = (L==0)? g_h256     : (L==1)? g_h128 : (L==2)? g_h64  : g_h32;
  extern __shared__ float smem[];
  float* in_sh = smem;             // RT*K
  float* wT = smem + RT*K;         // C*(KC+4), stride ==4 (mod 32): conflict-free
  int tid = threadIdx.x;
  int c = tid % C, rg = tid / C;
  int row0 = blockIdx.x * RT;
  for (int i = tid; i < RT*K; i += 256){
    int r = i / K, k = i % K;
    int row = row0 + r;
    in_sh[i] = (row < NN) ? in[row*K + k] : 0.f;
  }
  float acc[PR];
  float b = bias[c];
#pragma unroll
  for (int j = 0; j < PR; j++) acc[j] = b;
  for (int k0 = 0; k0 < K; k0 += KC){
    __syncthreads();
    for (int i = tid; i < KC*C; i += 256){
      int k = i / C, cc = i % C;
      wT[cc*(KC+4)+k] = Wg[(k0+k)*C + cc];
    }
    __syncthreads();
#pragma unroll 4
    for (int k = 0; k < KC; k += 4){
      float4 wv = *(const float4*)&wT[c*(KC+4)+k];
#pragma unroll
      for (int j = 0; j < PR; j++){
        int r = rg*PR + j;
        float4 a = *(const float4*)&in_sh[r*K + k0 + k];
        acc[j] += a.x*wv.x + a.y*wv.y + a.z*wv.z + a.w*wv.w;
      }
    }
  }
#pragma unroll
  for (int j = 0; j < PR; j++){
    int row = row0 + rg*PR + j;
    if (row < NN) out[row*C + c] = lrelu(acc[j]);
  }
}

// ---------------- sigmoid head ----------------
__global__ void k_head(const float* __restrict__ Wo, const float* __restrict__ bo,
                       float* __restrict__ out){
  __shared__ float w[32];
  if (threadIdx.x < 32) w[threadIdx.x] = Wo[threadIdx.x];
  __syncthreads();
  int n = blockIdx.x*blockDim.x + threadIdx.x;
  if (n >= NN) return;
  const float4* hp = (const float4*)(g_h32 + n*32);
  const float4* wp = (const float4*)w;
  float z = bo[0];
#pragma unroll
  for (int q = 0; q < 8; q++){
    float4 a = hp[q]; float4 ww = wp[q];
    z += a.x*ww.x + a.y*ww.y + a.z*ww.z + a.w*ww.w;
  }
  out[n] = 1.f/(1.f + expf(-z));
}

// ---------------- launch ----------------
extern "C" void kernel_launch(void* const* d_in, const int* in_sizes, int n_in,
                              void* d_out, int out_size){
  const float* x    = (const float*)d_in[0];
  const int*   col  = (const int*)d_in[1];
  const float* Wi0  = (const float*)d_in[2];
  const float* bi0  = (const float*)d_in[3];
  const float* gi0  = (const float*)d_in[4];
  const float* bei0 = (const float*)d_in[5];
  const float* Wi1  = (const float*)d_in[6];
  const float* bi1  = (const float*)d_in[7];
  const float* gi1  = (const float*)d_in[8];
  const float* bei1 = (const float*)d_in[9];
  const float* Wm   = (const float*)d_in[10];
  const float* bm   = (const float*)d_in[11];
  const float* gm   = (const float*)d_in[12];
  const float* bem  = (const float*)d_in[13];
  const float* Wu   = (const float*)d_in[14];
  const float* bu   = (const float*)d_in[15];
  const float* gu   = (const float*)d_in[16];
  const float* beu  = (const float*)d_in[17];
  const float* Wf0  = (const float*)d_in[18];
  const float* bf0  = (const float*)d_in[19];
  const float* Wf1  = (const float*)d_in[20];
  const float* bf1  = (const float*)d_in[21];
  const float* Wf2  = (const float*)d_in[22];
  const float* bf2  = (const float*)d_in[23];
  const float* Wf3  = (const float*)d_in[24];
  const float* bf3  = (const float*)d_in[25];
  const float* Wo   = (const float*)d_in[26];
  const float* bo   = (const float*)d_in[27];
  const int* src = col;
  const int* dst = col + EE;

  cudaFuncSetAttribute(k_mlp<1>, cudaFuncAttributeMaxDynamicSharedMemorySize, 100352);
  cudaFuncSetAttribute(k_mlp<2>, cudaFuncAttributeMaxDynamicSharedMemorySize, 99328);
  cudaFuncSetAttribute(k_mlp<3>, cudaFuncAttributeMaxDynamicSharedMemorySize, 74240);

  k_zero_stats<<<6,256>>>();
  k_init0<<<1184,256>>>(x, Wi0, bi0);
  k_finalize<<<1,32>>>(0, gi0, bei0);
  k_gemm<32,true><<<NN/32,256>>>(0, Wi1, bi1, /*out=B*/1, /*preslot*/0, /*outslot*/1);
  k_finalize<<<1,32>>>(1, gi1, bei1);
  k_actstore<<<1184,256>>>(1, -1, 0);                    // feats[0]

  for (int i = 0; i < 10; i++){
    int sm = 2 + 2*i, su = 3 + 2*i;
    k_gemm<32,false><<<NN/32,256>>>(i, Wm + i*1024, bm + i*32, /*out=A*/0, -1, sm);
    k_finalize<<<1,32>>>(sm, gm + i*32, bem + i*32);
    k_zero_agg<<<1184,256>>>();
    k_edge<<<(EE*8)/256,256>>>(sm, src, dst);
    k_gemm<64,false><<<NN/32,256>>>(i, Wu + i*2048, bu + i*32, /*out=B*/1, -1, su);
    k_finalize<<<1,32>>>(su, gu + i*32, beu + i*32);
    k_actstore<<<1184,256>>>(su, (i >= 2) ? (i-2) : -1, i+1);
  }

  k_mlp<0><<<(NN+31)/32,   256, 40960 >>>(Wf0, bf0);
  k_mlp<1><<<(NN+63)/64,   256, 100352>>>(Wf1, bf1);
  k_mlp<2><<<(NN+127)/128, 256, 99328 >>>(Wf2, bf2);
  k_mlp<3><<<(NN+255)/256, 256, 74240 >>>(Wf3, bf3);
  k_head<<<(NN+255)/256,256>>>(Wo, bo, (float*)d_out);
}

// round 2
// speedup vs baseline: 1.1221x; 1.1221x over previous
#include <cuda_runtime.h>
#include <math.h>

#define NN 100000
#define EE 1600000
#define NW (NN*32)

// ---------------- device scratch (static, no allocation) ----------------
__device__ __align__(16) float g_feats[11][NW];   // h after init + each layer
__device__ __align__(16) float g_preA[NW];        // pre-BN buffer A (msg pre)
__device__ __align__(16) float g_preB[NW];        // pre-BN buffer B (update pre)
__device__ __align__(16) float g_agg[NW];         // edge-aggregated messages
__device__ float g_stats[22][64];                 // [slot][0:32]=sum, [32:64]=sumsq
__device__ __align__(16) float g_scale[22][32];   // fused BN scale  = gamma*istd
__device__ __align__(16) float g_shift[22][32];   // fused BN shift  = beta - mean*scale
__device__ __align__(16) float g_h256[NN*256];
__device__ __align__(16) float g_h128[NN*128];
__device__ __align__(16) float g_h64[NN*64];
__device__ __align__(16) float g_h32[NW];
// CSR scratch
__device__ int g_deg[NN];
__device__ int g_cursor[NN];
__device__ int g_rowptr[NN+1];
__device__ int g_csrsrc[EE];

__device__ __forceinline__ float lrelu(float x){ return x > 0.f ? x : 0.01f*x; }

// ---------------- zero kernels ----------------
__global__ void k_zero_stats(){
  int i = blockIdx.x*blockDim.x + threadIdx.x;
  if (i < 22*64) ((float*)g_stats)[i] = 0.f;
  // also zero degree counters (100000 ints)
  int stride = gridDim.x*blockDim.x;
  for (int j = i; j < NN; j += stride) g_deg[j] = 0;
}

// ---------------- CSR build ----------------
__global__ void k_count(const int* __restrict__ dst){
  int i = blockIdx.x*blockDim.x + threadIdx.x;
  if (i < EE) atomicAdd(&g_deg[dst[i]], 1);
}

__global__ void k_scan(){
  __shared__ int partial[1024];
  const int CH = 98;   // 98*1024 >= 100000
  int t = threadIdx.x;
  int beg = t*CH, end = min(beg+CH, NN);
  int s = 0;
  for (int i = beg; i < end; i++) s += g_deg[i];
  partial[t] = s;
  __syncthreads();
  for (int off = 1; off < 1024; off <<= 1){
    int v = partial[t];
    int add = (t >= off) ? partial[t-off] : 0;
    __syncthreads();
    partial[t] = v + add;
    __syncthreads();
  }
  int run = (t > 0) ? partial[t-1] : 0;
  for (int i = beg; i < end; i++){
    g_rowptr[i] = run; g_cursor[i] = run;
    run += g_deg[i];
  }
  if (t == 1023) g_rowptr[NN] = partial[1023];
}

__global__ void k_fill(const int* __restrict__ src, const int* __restrict__ dst){
  int i = blockIdx.x*blockDim.x + threadIdx.x;
  if (i >= EE) return;
  int d = dst[i];
  int p = atomicAdd(&g_cursor[d], 1);
  g_csrsrc[p] = src[i];
}

// ---------------- per-block column-stat commit (256 threads, lane==column) -------
__device__ __forceinline__ void stats_commit(float s, float sq, int slot){
  __shared__ float red[2][8][32];
  int c = threadIdx.x & 31, w = threadIdx.x >> 5;
  red[0][w][c] = s; red[1][w][c] = sq;
  __syncthreads();
  if (w == 0){
    float a = 0.f, b = 0.f;
#pragma unroll
    for (int j = 0; j < 8; j++){ a += red[0][j][c]; b += red[1][j][c]; }
    atomicAdd(&g_stats[slot][c],    a);
    atomicAdd(&g_stats[slot][32+c], b);
  }
}

// ---------------- init layer 0: pre = x * Wi0 + bi0, stats slot 0 ----------------
__global__ void k_init0(const float* __restrict__ x, const float* __restrict__ W0,
                        const float* __restrict__ b0){
  int c = threadIdx.x & 31;
  float wc = W0[c], bc = b0[c];
  float s = 0.f, sq = 0.f;
  int stride = gridDim.x*blockDim.x;
  for (int idx = blockIdx.x*blockDim.x + threadIdx.x; idx < NW; idx += stride){
    float v = fmaf(x[idx >> 5], wc, bc);
    g_preA[idx] = v; s += v; sq += v*v;
  }
  stats_commit(s, sq, 0);
}

// ---------------- finalize BN stats into fused scale/shift ----------------
__global__ void k_finalize(int slot, const float* __restrict__ g,
                           const float* __restrict__ be){
  int c = threadIdx.x;
  float m = g_stats[slot][c] * (1.f/NN);
  float v = g_stats[slot][32+c] * (1.f/NN) - m*m;
  float istd = rsqrtf(v + 1e-5f);
  float sc = g[c]*istd;
  g_scale[slot][c] = sc;
  g_shift[slot][c] = fmaf(-m, sc, be[c]);
}

// ---------------- register-weight small GEMM --------------------------------------
// out[N,32] = act(in)[N,K] @ W[K,32] + b, with per-column stats into outslot.
// lane = output column; weights live in registers; input rows broadcast via LDS.
template<int K, bool PRE>
__global__ void __launch_bounds__(256) k_gemm2(int fidx, const float* __restrict__ Wg,
        const float* __restrict__ bias, int outsel, int preslot, int outslot)
{
  __shared__ float in_sh[8][4][K];
  const float* in1 = PRE ? g_preA : g_feats[fidx];
  float* out = outsel ? g_preB : g_preA;
  int lane = threadIdx.x & 31, w = threadIdx.x >> 5;
  float wreg[K];
#pragma unroll
  for (int k = 0; k < K; k++) wreg[k] = Wg[k*32 + lane];
  float b = bias[lane];
  float psc = 0.f, psh = 0.f;
  if (PRE){ psc = g_scale[preslot][lane]; psh = g_shift[preslot][lane]; }
  float s = 0.f, sq = 0.f;
  int gwarp  = blockIdx.x*8 + w;
  int nwarps = gridDim.x*8;
  for (int grp = gwarp; grp < NN/4; grp += nwarps){
    int r0 = grp*4;
#pragma unroll
    for (int j = 0; j < 4; j++){
      float v = in1[(r0+j)*32 + lane];
      if (PRE) v = lrelu(fmaf(v, psc, psh));
      in_sh[w][j][lane] = v;
      if (K == 64) in_sh[w][j][32 + lane] = g_agg[(r0+j)*32 + lane];
    }
    __syncwarp();
    float a0=b, a1=b, a2=b, a3=b;
#pragma unroll
    for (int k = 0; k < K; k += 4){
      float4 x0 = *(const float4*)&in_sh[w][0][k];
      float4 x1 = *(const float4*)&in_sh[w][1][k];
      float4 x2 = *(const float4*)&in_sh[w][2][k];
      float4 x3 = *(const float4*)&in_sh[w][3][k];
      a0 = fmaf(x0.x,wreg[k],a0); a0 = fmaf(x0.y,wreg[k+1],a0);
      a0 = fmaf(x0.z,wreg[k+2],a0); a0 = fmaf(x0.w,wreg[k+3],a0);
      a1 = fmaf(x1.x,wreg[k],a1); a1 = fmaf(x1.y,wreg[k+1],a1);
      a1 = fmaf(x1.z,wreg[k+2],a1); a1 = fmaf(x1.w,wreg[k+3],a1);
      a2 = fmaf(x2.x,wreg[k],a2); a2 = fmaf(x2.y,wreg[k+1],a2);
      a2 = fmaf(x2.z,wreg[k+2],a2); a2 = fmaf(x2.w,wreg[k+3],a2);
      a3 = fmaf(x3.x,wreg[k],a3); a3 = fmaf(x3.y,wreg[k+1],a3);
      a3 = fmaf(x3.z,wreg[k+2],a3); a3 = fmaf(x3.w,wreg[k+3],a3);
    }
    __syncwarp();
    out[(r0+0)*32+lane] = a0;
    out[(r0+1)*32+lane] = a1;
    out[(r0+2)*32+lane] = a2;
    out[(r0+3)*32+lane] = a3;
    s  += a0+a1+a2+a3;
    sq += a0*a0+a1*a1+a2*a2+a3*a3;
  }
  stats_commit(s, sq, outslot);
}

// ---------------- CSR pull-gather: agg[d] = sum_{e: dst=d} lrelu(bn(preA[src])) ----
__global__ void __launch_bounds__(256) k_gather(int slot){
  int warp = (blockIdx.x*blockDim.x + threadIdx.x) >> 5;
  int lane = threadIdx.x & 31;
  if (warp >= NN) return;
  float sc = g_scale[slot][lane], sh = g_shift[slot][lane];
  int beg = g_rowptr[warp], end = g_rowptr[warp+1];
  float acc = 0.f;
  for (int base = beg; base < end; base += 32){
    int nb = min(32, end - base);
    int s_l = (base + lane < end) ? g_csrsrc[base + lane] : 0;
    for (int j = 0; j < nb; j++){
      int s = __shfl_sync(0xffffffffu, s_l, j);
      float v = g_preA[s*32 + lane];
      acc += lrelu(fmaf(v, sc, sh));
    }
  }
  g_agg[warp*32 + lane] = acc;
}

// ---------------- apply BN+lrelu (+residual) to g_preB -> feats[oidx] ----------------
__global__ void k_actstore(int slot, int ridx, int oidx){
  int c = threadIdx.x & 31;
  float sc = g_scale[slot][c], sh = g_shift[slot][c];
  const float* resid = (ridx >= 0) ? g_feats[ridx] : (const float*)0;
  float* dstp = g_feats[oidx];
  int stride = gridDim.x*blockDim.x;
  for (int i = blockIdx.x*blockDim.x + threadIdx.x; i < NW; i += stride){
    float v = lrelu(fmaf(g_preB[i], sc, sh));
    if (ridx >= 0) v += resid[i];
    dstp[i] = v;
  }
}

// ---------------- final MLP tiled GEMM (no BN): out = lrelu(in @ W + b) -------------
template<int L> struct MC;
template<> struct MC<0>{ static constexpr int K=32,  C=256, KC=32;  };
template<> struct MC<1>{ static constexpr int K=256, C=128, KC=64;  };
template<> struct MC<2>{ static constexpr int K=128, C=64,  KC=128; };
template<> struct MC<3>{ static constexpr int K=64,  C=32,  KC=64;  };

template<int L>
__global__ void __launch_bounds__(256) k_mlp(const float* __restrict__ Wg,
                                             const float* __restrict__ bias)
{
  constexpr int K = MC<L>::K, C = MC<L>::C, KC = MC<L>::KC;
  constexpr int PR = 32;
  constexpr int RSUB = 256/C;
  constexpr int RT = PR*RSUB;
  const float* in = (L==0)? g_feats[10] : (L==1)? g_h256 : (L==2)? g_h128 : g_h64;
  float* out      = (L==0)? g_h256     : (L==1)? g_h128 : (L==2)? g_h64  : g_h32;
  extern __shared__ float smem[];
  float* in_sh = smem;             // RT*K
  float* wT = smem + RT*K;         // C*(KC+4)
  int tid = threadIdx.x;
  int c = tid % C, rg = tid / C;
  int row0 = blockIdx.x * RT;
  for (int i = tid; i < RT*K; i += 256){
    int r = i / K, k = i % K;
    int row = row0 + r;
    in_sh[i] = (row < NN) ? in[row*K + k] : 0.f;
  }
  float acc[PR];
  float b = bias[c];
#pragma unroll
  for (int j = 0; j < PR; j++) acc[j] = b;
  for (int k0 = 0; k0 < K; k0 += KC){
    __syncthreads();
    for (int i = tid; i < KC*C; i += 256){
      int k = i / C, cc = i % C;
      wT[cc*(KC+4)+k] = Wg[(k0+k)*C + cc];
    }
    __syncthreads();
#pragma unroll 4
    for (int k = 0; k < KC; k += 4){
      float4 wv = *(const float4*)&wT[c*(KC+4)+k];
#pragma unroll
      for (int j = 0; j < PR; j++){
        int r = rg*PR + j;
        float4 a = *(const float4*)&in_sh[r*K + k0 + k];
        acc[j] += a.x*wv.x + a.y*wv.y + a.z*wv.z + a.w*wv.w;
      }
    }
  }
#pragma unroll
  for (int j = 0; j < PR; j++){
    int row = row0 + rg*PR + j;
    if (row < NN) out[row*C + c] = lrelu(acc[j]);
  }
}

// ---------------- sigmoid head ----------------
__global__ void k_head(const float* __restrict__ Wo, const float* __restrict__ bo,
                       float* __restrict__ out){
  __shared__ float w[32];
  if (threadIdx.x < 32) w[threadIdx.x] = Wo[threadIdx.x];
  __syncthreads();
  int n = blockIdx.x*blockDim.x + threadIdx.x;
  if (n >= NN) return;
  const float4* hp = (const float4*)(g_h32 + n*32);
  const float4* wp = (const float4*)w;
  float z = bo[0];
#pragma unroll
  for (int q = 0; q < 8; q++){
    float4 a = hp[q]; float4 ww = wp[q];
    z += a.x*ww.x + a.y*ww.y + a.z*ww.z + a.w*ww.w;
  }
  out[n] = 1.f/(1.f + expf(-z));
}

// ---------------- launch ----------------
extern "C" void kernel_launch(void* const* d_in, const int* in_sizes, int n_in,
                              void* d_out, int out_size){
  const float* x    = (const float*)d_in[0];
  const int*   col  = (const int*)d_in[1];
  const float* Wi0  = (const float*)d_in[2];
  const float* bi0  = (const float*)d_in[3];
  const float* gi0  = (const float*)d_in[4];
  const float* bei0 = (const float*)d_in[5];
  const float* Wi1  = (const float*)d_in[6];
  const float* bi1  = (const float*)d_in[7];
  const float* gi1  = (const float*)d_in[8];
  const float* bei1 = (const float*)d_in[9];
  const float* Wm   = (const float*)d_in[10];
  const float* bm   = (const float*)d_in[11];
  const float* gm   = (const float*)d_in[12];
  const float* bem  = (const float*)d_in[13];
  const float* Wu   = (const float*)d_in[14];
  const float* bu   = (const float*)d_in[15];
  const float* gu   = (const float*)d_in[16];
  const float* beu  = (const float*)d_in[17];
  const float* Wf0  = (const float*)d_in[18];
  const float* bf0  = (const float*)d_in[19];
  const float* Wf1  = (const float*)d_in[20];
  const float* bf1  = (const float*)d_in[21];
  const float* Wf2  = (const float*)d_in[22];
  const float* bf2  = (const float*)d_in[23];
  const float* Wf3  = (const float*)d_in[24];
  const float* bf3  = (const float*)d_in[25];
  const float* Wo   = (const float*)d_in[26];
  const float* bo   = (const float*)d_in[27];
  const int* src = col;
  const int* dst = col + EE;

  cudaFuncSetAttribute(k_mlp<1>, cudaFuncAttributeMaxDynamicSharedMemorySize, 100352);
  cudaFuncSetAttribute(k_mlp<2>, cudaFuncAttributeMaxDynamicSharedMemorySize, 99328);
  cudaFuncSetAttribute(k_mlp<3>, cudaFuncAttributeMaxDynamicSharedMemorySize, 74240);

  // CSR build (order within a node is irrelevant up to fp rounding)
  k_zero_stats<<<440,256>>>();
  k_count<<<(EE+255)/256,256>>>(dst);
  k_scan<<<1,1024>>>();
  k_fill<<<(EE+255)/256,256>>>(src, dst);

  // init MLP
  k_init0<<<1184,256>>>(x, Wi0, bi0);
  k_finalize<<<1,32>>>(0, gi0, bei0);
  k_gemm2<32,true><<<296,256>>>(0, Wi1, bi1, /*out=B*/1, /*preslot*/0, /*outslot*/1);
  k_finalize<<<1,32>>>(1, gi1, bei1);
  k_actstore<<<1184,256>>>(1, -1, 0);                    // feats[0]

  for (int i = 0; i < 10; i++){
    int sm = 2 + 2*i, su = 3 + 2*i;
    k_gemm2<32,false><<<296,256>>>(i, Wm + i*1024, bm + i*32, /*out=A*/0, -1, sm);
    k_finalize<<<1,32>>>(sm, gm + i*32, bem + i*32);
    k_gather<<<(NN*32+255)/256,256>>>(sm);
    k_gemm2<64,false><<<296,256>>>(i, Wu + i*2048, bu + i*32, /*out=B*/1, -1, su);
    k_finalize<<<1,32>>>(su, gu + i*32, beu + i*32);
    k_actstore<<<1184,256>>>(su, (i >= 2) ? (i-2) : -1, i+1);
  }

  k_mlp<0><<<(NN+31)/32,   256, 40960 >>>(Wf0, bf0);
  k_mlp<1><<<(NN+63)/64,   256, 100352>>>(Wf1, bf1);
  k_mlp<2><<<(NN+127)/128, 256, 99328 >>>(Wf2, bf2);
  k_mlp<3><<<(NN+255)/256, 256, 74240 >>>(Wf3, bf3);
  k_head<<<(NN+255)/256,256>>>(Wo, bo, (float*)d_out);
}